// round 1
// baseline (speedup 1.0000x reference)
#include <cuda_runtime.h>
#include <cstdint>

// Problem constants (from reference setup_inputs)
#define N_   2
#define C_   256
#define H_   200
#define W_   200
#define PH_  7
#define PW_  7
#define NBIN 49
#define SCALE 0.25f

// NHWC scratch: 2*200*200*256 floats = 81.92 MB
__device__ float g_nhwc[(size_t)N_ * H_ * W_ * C_];

// ---------------------------------------------------------------------------
// Kernel 1: NCHW -> NHWC transpose, tiled over the (C, W) plane per (n,h).
// grid = (ceil(W/32)=7, C/32=8, N*H=400), block = (32,8)
// ---------------------------------------------------------------------------
__global__ __launch_bounds__(256) void transpose_nchw_nhwc(
    const float* __restrict__ in)
{
    __shared__ float tile[32][33];
    const int p  = blockIdx.z;           // n*H + h
    const int n  = p / H_;
    const int h  = p % H_;
    const int w0 = blockIdx.x * 32;
    const int c0 = blockIdx.y * 32;
    const int tx = threadIdx.x;          // 0..31
    const int ty = threadIdx.y;          // 0..7

    // Read: coalesced along W
    #pragma unroll
    for (int i = 0; i < 4; ++i) {
        const int c = c0 + ty + i * 8;
        const int w = w0 + tx;
        if (w < W_)
            tile[ty + i * 8][tx] =
                in[(((size_t)n * C_ + c) * H_ + h) * W_ + w];
    }
    __syncthreads();

    // Write: coalesced along C
    #pragma unroll
    for (int i = 0; i < 4; ++i) {
        const int w = w0 + ty + i * 8;
        if (w < W_)
            g_nhwc[(((size_t)p) * W_ + w) * C_ + c0 + tx] = tile[tx][ty + i * 8];
    }
}

// ---------------------------------------------------------------------------
// Kernel 2: RoIAlign from NHWC. One block per ROI, 256 threads.
// Warp w (0..7) owns bins {w, w+8, ...}; lane owns 4 channels via float4.
// Two passes of 128 channels each; smem staging [c][bin] padded to 53 for a
// conflict-free coalesced copy-out.
// ---------------------------------------------------------------------------
__global__ __launch_bounds__(256) void roialign_kernel(
    const float* __restrict__ rois,
    float* __restrict__ out, int K)
{
    __shared__ float sout[128 * 53];   // 27.1 KB

    const int k = blockIdx.x;
    if (k >= K) return;

    const float bf = rois[(size_t)k * 5 + 0];
    const float x1 = rois[(size_t)k * 5 + 1] * SCALE;
    const float y1 = rois[(size_t)k * 5 + 2] * SCALE;
    const float x2 = rois[(size_t)k * 5 + 3] * SCALE;
    const float y2 = rois[(size_t)k * 5 + 4] * SCALE;
    const int  bi  = (int)bf;

    const float roi_w = fmaxf(x2 - x1, 1.0f);
    const float roi_h = fmaxf(y2 - y1, 1.0f);
    const float bin_w = roi_w * (1.0f / PW_);
    const float bin_h = roi_h * (1.0f / PH_);

    const float* __restrict__ base =
        g_nhwc + (size_t)bi * H_ * W_ * C_;

    const int tid  = threadIdx.x;
    const int lane = tid & 31;
    const int wg   = tid >> 5;     // 0..7 bin group

    for (int pass = 0; pass < 2; ++pass) {
        const int c = pass * 128 + lane * 4;   // global channel
        const int cc = lane * 4;               // channel within pass

        for (int bin = wg; bin < NBIN; bin += 8) {
            const int ph = bin / PW_;
            const int pw = bin - ph * PW_;

            float ax = 0.f, ay = 0.f, az = 0.f, aw = 0.f;

            #pragma unroll
            for (int sy = 0; sy < 2; ++sy) {
                const float oy = (float)ph + ((float)sy + 0.5f) * 0.5f;
                const float yv = y1 + oy * bin_h;
                const bool  vy = (yv >= -1.0f) && (yv <= (float)H_);
                const float y0 = fmaxf(yv, 0.0f);
                int   yl = (int)floorf(y0);
                yl = yl > (H_ - 1) ? (H_ - 1) : yl;
                const int   yh = yl + 1 > (H_ - 1) ? (H_ - 1) : yl + 1;
                const float ly = y0 - (float)yl;
                const float hy = 1.0f - ly;

                #pragma unroll
                for (int sx = 0; sx < 2; ++sx) {
                    const float ox = (float)pw + ((float)sx + 0.5f) * 0.5f;
                    const float xv = x1 + ox * bin_w;
                    const bool  vx = (xv >= -1.0f) && (xv <= (float)W_);
                    const float x0 = fmaxf(xv, 0.0f);
                    int   xl = (int)floorf(x0);
                    xl = xl > (W_ - 1) ? (W_ - 1) : xl;
                    const int   xh = xl + 1 > (W_ - 1) ? (W_ - 1) : xl + 1;
                    const float lx = x0 - (float)xl;
                    const float hx = 1.0f - lx;

                    const float m  = (vy && vx) ? 1.0f : 0.0f;
                    const float w1 = hy * hx * m;
                    const float w2 = hy * lx * m;
                    const float w3 = ly * hx * m;
                    const float w4 = ly * lx * m;

                    const float4 v1 = *(const float4*)(base + ((size_t)(yl * W_ + xl) * C_ + c));
                    const float4 v2 = *(const float4*)(base + ((size_t)(yl * W_ + xh) * C_ + c));
                    const float4 v3 = *(const float4*)(base + ((size_t)(yh * W_ + xl) * C_ + c));
                    const float4 v4 = *(const float4*)(base + ((size_t)(yh * W_ + xh) * C_ + c));

                    ax += w1 * v1.x + w2 * v2.x + w3 * v3.x + w4 * v4.x;
                    ay += w1 * v1.y + w2 * v2.y + w3 * v3.y + w4 * v4.y;
                    az += w1 * v1.z + w2 * v2.z + w3 * v3.z + w4 * v4.z;
                    aw += w1 * v1.w + w2 * v2.w + w3 * v3.w + w4 * v4.w;
                }
            }

            sout[(cc + 0) * 53 + bin] = ax * 0.25f;
            sout[(cc + 1) * 53 + bin] = ay * 0.25f;
            sout[(cc + 2) * 53 + bin] = az * 0.25f;
            sout[(cc + 3) * 53 + bin] = aw * 0.25f;
        }
        __syncthreads();

        // Coalesced copy-out of 128 channels * 49 bins = 6272 floats
        float* __restrict__ o = out + (size_t)k * (C_ * NBIN) + pass * (128 * NBIN);
        #pragma unroll 4
        for (int e = tid; e < 128 * NBIN; e += 256) {
            const int cch = e / NBIN;
            const int bn  = e - cch * NBIN;
            o[e] = sout[cch * 53 + bn];
        }
        __syncthreads();
    }
}

// ---------------------------------------------------------------------------
extern "C" void kernel_launch(void* const* d_in, const int* in_sizes, int n_in,
                              void* d_out, int out_size)
{
    const float* inp  = (const float*)d_in[0];
    const float* rois = (const float*)d_in[1];
    float* out        = (float*)d_out;
    const int K = in_sizes[1] / 5;

    dim3 tb(32, 8);
    dim3 tg((W_ + 31) / 32, C_ / 32, N_ * H_);
    transpose_nchw_nhwc<<<tg, tb>>>(inp);

    roialign_kernel<<<K, 256>>>(rois, out, K);
}

// round 2
// speedup vs baseline: 1.0044x; 1.0044x over previous
#include <cuda_runtime.h>
#include <cstdint>

// Problem constants (from reference setup_inputs)
#define N_   2
#define C_   256
#define H_   200
#define W_   200
#define PH_  7
#define PW_  7
#define NBIN 49
#define SCALE 0.25f

// NHWC scratch: 2*200*200*256 floats = 81.92 MB
__device__ float g_nhwc[(size_t)N_ * H_ * W_ * C_];

// ---------------------------------------------------------------------------
// Kernel 1: NCHW -> NHWC transpose, tiled over the (C, W) plane per (n,h).
// grid = (ceil(W/32)=7, C/32=8, N*H=400), block = (32,8)
// ---------------------------------------------------------------------------
__global__ __launch_bounds__(256) void transpose_nchw_nhwc(
    const float* __restrict__ in)
{
    __shared__ float tile[32][33];
    const int p  = blockIdx.z;           // n*H + h
    const int n  = p / H_;
    const int h  = p % H_;
    const int w0 = blockIdx.x * 32;
    const int c0 = blockIdx.y * 32;
    const int tx = threadIdx.x;          // 0..31
    const int ty = threadIdx.y;          // 0..7

    // Read: coalesced along W
    #pragma unroll
    for (int i = 0; i < 4; ++i) {
        const int c = c0 + ty + i * 8;
        const int w = w0 + tx;
        if (w < W_)
            tile[ty + i * 8][tx] =
                in[(((size_t)n * C_ + c) * H_ + h) * W_ + w];
    }
    __syncthreads();

    // Write: coalesced along C
    #pragma unroll
    for (int i = 0; i < 4; ++i) {
        const int w = w0 + ty + i * 8;
        if (w < W_)
            g_nhwc[(((size_t)p) * W_ + w) * C_ + c0 + tx] = tile[tx][ty + i * 8];
    }
}

// ---------------------------------------------------------------------------
// Kernel 2: RoIAlign from NHWC. One block per ROI, 256 threads.
// Warp w (0..7) owns bins {w, w+8, ...}; lane owns 4 channels via float4.
// Two passes of 128 channels each; smem staging [c][bin] padded to 53 for a
// conflict-free coalesced copy-out.
// ---------------------------------------------------------------------------
__global__ __launch_bounds__(256) void roialign_kernel(
    const float* __restrict__ rois,
    float* __restrict__ out, int K)
{
    __shared__ float sout[128 * 53];   // 27.1 KB

    const int k = blockIdx.x;
    if (k >= K) return;

    const float bf = rois[(size_t)k * 5 + 0];
    const float x1 = rois[(size_t)k * 5 + 1] * SCALE;
    const float y1 = rois[(size_t)k * 5 + 2] * SCALE;
    const float x2 = rois[(size_t)k * 5 + 3] * SCALE;
    const float y2 = rois[(size_t)k * 5 + 4] * SCALE;
    const int  bi  = (int)bf;

    const float roi_w = fmaxf(x2 - x1, 1.0f);
    const float roi_h = fmaxf(y2 - y1, 1.0f);
    const float bin_w = roi_w * (1.0f / PW_);
    const float bin_h = roi_h * (1.0f / PH_);

    const float* __restrict__ base =
        g_nhwc + (size_t)bi * H_ * W_ * C_;

    const int tid  = threadIdx.x;
    const int lane = tid & 31;
    const int wg   = tid >> 5;     // 0..7 bin group

    for (int pass = 0; pass < 2; ++pass) {
        const int c = pass * 128 + lane * 4;   // global channel
        const int cc = lane * 4;               // channel within pass

        for (int bin = wg; bin < NBIN; bin += 8) {
            const int ph = bin / PW_;
            const int pw = bin - ph * PW_;

            float ax = 0.f, ay = 0.f, az = 0.f, aw = 0.f;

            #pragma unroll
            for (int sy = 0; sy < 2; ++sy) {
                const float oy = (float)ph + ((float)sy + 0.5f) * 0.5f;
                const float yv = y1 + oy * bin_h;
                const bool  vy = (yv >= -1.0f) && (yv <= (float)H_);
                const float y0 = fmaxf(yv, 0.0f);
                int   yl = (int)floorf(y0);
                yl = yl > (H_ - 1) ? (H_ - 1) : yl;
                const int   yh = yl + 1 > (H_ - 1) ? (H_ - 1) : yl + 1;
                const float ly = y0 - (float)yl;
                const float hy = 1.0f - ly;

                #pragma unroll
                for (int sx = 0; sx < 2; ++sx) {
                    const float ox = (float)pw + ((float)sx + 0.5f) * 0.5f;
                    const float xv = x1 + ox * bin_w;
                    const bool  vx = (xv >= -1.0f) && (xv <= (float)W_);
                    const float x0 = fmaxf(xv, 0.0f);
                    int   xl = (int)floorf(x0);
                    xl = xl > (W_ - 1) ? (W_ - 1) : xl;
                    const int   xh = xl + 1 > (W_ - 1) ? (W_ - 1) : xl + 1;
                    const float lx = x0 - (float)xl;
                    const float hx = 1.0f - lx;

                    const float m  = (vy && vx) ? 1.0f : 0.0f;
                    const float w1 = hy * hx * m;
                    const float w2 = hy * lx * m;
                    const float w3 = ly * hx * m;
                    const float w4 = ly * lx * m;

                    const float4 v1 = *(const float4*)(base + ((size_t)(yl * W_ + xl) * C_ + c));
                    const float4 v2 = *(const float4*)(base + ((size_t)(yl * W_ + xh) * C_ + c));
                    const float4 v3 = *(const float4*)(base + ((size_t)(yh * W_ + xl) * C_ + c));
                    const float4 v4 = *(const float4*)(base + ((size_t)(yh * W_ + xh) * C_ + c));

                    ax += w1 * v1.x + w2 * v2.x + w3 * v3.x + w4 * v4.x;
                    ay += w1 * v1.y + w2 * v2.y + w3 * v3.y + w4 * v4.y;
                    az += w1 * v1.z + w2 * v2.z + w3 * v3.z + w4 * v4.z;
                    aw += w1 * v1.w + w2 * v2.w + w3 * v3.w + w4 * v4.w;
                }
            }

            sout[(cc + 0) * 53 + bin] = ax * 0.25f;
            sout[(cc + 1) * 53 + bin] = ay * 0.25f;
            sout[(cc + 2) * 53 + bin] = az * 0.25f;
            sout[(cc + 3) * 53 + bin] = aw * 0.25f;
        }
        __syncthreads();

        // Coalesced copy-out of 128 channels * 49 bins = 6272 floats
        float* __restrict__ o = out + (size_t)k * (C_ * NBIN) + pass * (128 * NBIN);
        #pragma unroll 4
        for (int e = tid; e < 128 * NBIN; e += 256) {
            const int cch = e / NBIN;
            const int bn  = e - cch * NBIN;
            o[e] = sout[cch * 53 + bn];
        }
        __syncthreads();
    }
}

// ---------------------------------------------------------------------------
extern "C" void kernel_launch(void* const* d_in, const int* in_sizes, int n_in,
                              void* d_out, int out_size)
{
    const float* inp  = (const float*)d_in[0];
    const float* rois = (const float*)d_in[1];
    float* out        = (float*)d_out;
    const int K = in_sizes[1] / 5;

    dim3 tb(32, 8);
    dim3 tg((W_ + 31) / 32, C_ / 32, N_ * H_);
    transpose_nchw_nhwc<<<tg, tb>>>(inp);

    roialign_kernel<<<K, 256>>>(rois, out, K);
}